// round 11
// baseline (speedup 1.0000x reference)
#include <cuda_runtime.h>
#include <cuda_fp16.h>
#include <math.h>
#include <stdint.h>

#define EE 64
#define SSZ 128
#define FF 640
#define HH 256
#define GG 768          // 3*H
#define LLN 20
#define CC 32
#define BB (EE*SSZ)     // 8192
#define BLM (BB*LLN)    // 163840
#define EPSV 1e-5f

// ---------------- scratch (static __device__, no allocation) ----------------
__device__ __half g_xh [BB*FF];     // input converted, 10 MB
__device__ __half g_x16[BB*HH];
__device__ __half g_gi16[BB*GG];
__device__ __half g_gh16[BB*GG];
__device__ __half g_h16[BB*HH];
__device__ __half g_hs16[BLM*HH];   // 80 MB, BN2+PReLU already applied
__device__ __half g_y216[BLM*HH];   // 80 MB
__device__ __half g_wlin16[HH*FF];
__device__ __half g_wih16[GG*HH];
__device__ __half g_whh16[GG*HH];
__device__ __half g_wc16[HH*HH];
__device__ __half g_wmu16[CC*HH];
__device__ float g_s1[HH], g_o1[HH];
__device__ float g_s2[HH], g_o2[HH];
__device__ float g_s3[HH], g_o3[HH];
__device__ float g_al[3];

// ---------------- helpers ----------------------------------------------------
__device__ __forceinline__ uint32_t cvta_s(const void* p) {
    return (uint32_t)__cvta_generic_to_shared(p);
}
__device__ __forceinline__ void mma16(float* c, const uint32_t* a, const uint32_t* b) {
    asm volatile("mma.sync.aligned.m16n8k16.row.col.f32.f16.f16.f32 "
        "{%0,%1,%2,%3},{%4,%5,%6,%7},{%8,%9},{%0,%1,%2,%3};"
        : "+f"(c[0]), "+f"(c[1]), "+f"(c[2]), "+f"(c[3])
        : "r"(a[0]), "r"(a[1]), "r"(a[2]), "r"(a[3]), "r"(b[0]), "r"(b[1]));
}
#define LDSM4(r0,r1,r2,r3,addr) \
    asm volatile("ldmatrix.sync.aligned.m8n8.x4.shared.b16 {%0,%1,%2,%3}, [%4];" \
        : "=r"(r0),"=r"(r1),"=r"(r2),"=r"(r3) : "r"(addr))
#define CP_ASYNC16(dst, src) \
    asm volatile("cp.async.ca.shared.global [%0], [%1], 16;" :: "r"(dst), "l"(src))
#define CP_COMMIT() asm volatile("cp.async.commit_group;" ::)
#define CP_WAIT1()  asm volatile("cp.async.wait_group 1;" ::)

__device__ __forceinline__ float sigf(float x) { return 1.f / (1.f + expf(-x)); }
__device__ __forceinline__ float2 h2f(uint32_t u) { return __half22float2(*(__half2*)&u); }
__device__ __forceinline__ uint32_t f2h(float a, float b) {
    __half2 h = __floats2half2_rn(a, b); return *(uint32_t*)&h;
}

// ---------------- prep ------------------------------------------------------
__global__ void prep_kernel(const float* g1,const float* b1,const float* m1,const float* v1,const float* a1,
                            const float* g2,const float* b2,const float* m2,const float* v2,const float* a2,
                            const float* g3,const float* b3,const float* m3,const float* v3,const float* a3)
{
    int i = threadIdx.x;
    float s;
    s = g1[i] / sqrtf(v1[i] + EPSV); g_s1[i] = s; g_o1[i] = b1[i] - m1[i]*s;
    s = g2[i] / sqrtf(v2[i] + EPSV); g_s2[i] = s; g_o2[i] = b2[i] - m2[i]*s;
    s = g3[i] / sqrtf(v3[i] + EPSV); g_s3[i] = s; g_o3[i] = b3[i] - m3[i]*s;
    if (i == 0) { g_al[0] = a1[0]; g_al[1] = a2[0]; g_al[2] = a3[0]; }
}

// convert n8*8 floats -> halfs
__global__ void cvt_kernel(const float* __restrict__ s, __half* __restrict__ d, int n8)
{
    int i = blockIdx.x * blockDim.x + threadIdx.x;
    if (i >= n8) return;
    float4 v0 = *(const float4*)(s + i*8);
    float4 v1 = *(const float4*)(s + i*8 + 4);
    uint4 u = make_uint4(f2h(v0.x,v0.y), f2h(v0.z,v0.w), f2h(v1.x,v1.y), f2h(v1.z,v1.w));
    *(uint4*)(d + i*8) = u;
}

__global__ void zero_h_kernel()
{
    int i = blockIdx.x * blockDim.x + threadIdx.x;   // BB*HH/8
    *(uint4*)(g_h16 + (size_t)i*8) = make_uint4(0,0,0,0);
}

// ---------------- all-fp16 GEMM, cp.async 3-stage pipeline -------------------
// C = epi(A @ W^T + bias). A:[M,K], W:[N,K] fp16 row-major. BK=32, pitch 40
// halfs (80B, ldmatrix conflict-free). 256 thr = 8 warps WM x WN.
// MODE 0: bias. MODE 1: bias+BN1+PReLU. MODE 3: bias+BN3+PReLU.
// OUTH: fp16 output, else fp32.
template<int BM,int BN,int WM,int WN,int MODE,bool OUTH>
__global__ __launch_bounds__(256, 2) void hgemm2(
    const __half* __restrict__ A, const __half* __restrict__ W,
    const float* __restrict__ bias, void* __restrict__ Cst,
    int M, int N, int K)
{
    constexpr int PIT = 40;
    extern __shared__ __half smh[];
    __half* Ah = smh;                       // [3][BM*PIT]
    __half* Wh = smh + 3*BM*PIT;            // [3][BN*PIT]

    const int tid  = threadIdx.x;
    const int wid  = tid >> 5;
    const int lane = tid & 31;
    const int wm   = wid % WM;
    const int wn   = wid / WM;
    constexpr int WTM = BM / WM;
    constexpr int WTN = BN / WN;
    constexpr int MT  = WTM / 16;
    constexpr int NT  = WTN / 8;            // even
    const int qr = lane >> 2, qc = lane & 3;
    const int l8 = lane & 7;

    const int m0 = blockIdx.y * BM;
    const int n0 = blockIdx.x * BN;

    constexpr int ACH = BM * 4;             // 16B chunks per tile
    constexpr int WCH = BN * 4;
    constexpr int AIT = ACH / 256;
    constexpr int WIT = (WCH + 255) / 256;

    float acc[MT][NT][4];
#pragma unroll
    for (int i = 0; i < MT; i++)
#pragma unroll
        for (int j = 0; j < NT; j++)
#pragma unroll
            for (int q = 0; q < 4; q++) acc[i][j][q] = 0.f;

    const int T = K / 32;

#define ISSUE_STAGE(st, t) do { \
        _Pragma("unroll") \
        for (int it = 0; it < AIT; it++) { \
            int idx = tid + it*256; int r = idx >> 2, c = idx & 3; \
            uint32_t ds = cvta_s(&Ah[(st)*BM*PIT + r*PIT + c*8]); \
            CP_ASYNC16(ds, A + (size_t)(m0 + r) * K + (t)*32 + c*8); \
        } \
        _Pragma("unroll") \
        for (int it = 0; it < WIT; it++) { \
            int idx = tid + it*256; \
            if ((WCH % 256 == 0) || idx < WCH) { \
                int r = idx >> 2, c = idx & 3; \
                uint32_t ds = cvta_s(&Wh[(st)*BN*PIT + r*PIT + c*8]); \
                CP_ASYNC16(ds, W + (size_t)(n0 + r) * K + (t)*32 + c*8); \
            } \
        } \
        CP_COMMIT(); \
    } while (0)

    ISSUE_STAGE(0, 0);
    if (T > 1) { ISSUE_STAGE(1, 1); } else { CP_COMMIT(); }

    for (int t = 0; t < T; t++) {
        CP_WAIT1();
        __syncthreads();
        const int buf = t % 3;
        const __half* Ab = Ah + buf*BM*PIT;
        const __half* Wb = Wh + buf*BN*PIT;

#pragma unroll
        for (int ks = 0; ks < 2; ks++) {
            uint32_t af[MT][4], bf[NT][2];
#pragma unroll
            for (int mt = 0; mt < MT; mt++) {
                const int m  = wm*WTM + mt*16 + l8 + ((lane >> 3) & 1) * 8;
                const int ck = 2*ks + (lane >> 4);
                uint32_t ad = cvta_s(&Ab[m*PIT + ck*8]);
                LDSM4(af[mt][0], af[mt][1], af[mt][2], af[mt][3], ad);
            }
#pragma unroll
            for (int np = 0; np < NT/2; np++) {
                const int n  = wn*WTN + np*16 + l8 + ((lane >> 4) & 1) * 8;
                const int ck = 2*ks + ((lane >> 3) & 1);
                uint32_t bd = cvta_s(&Wb[n*PIT + ck*8]);
                LDSM4(bf[2*np][0], bf[2*np][1], bf[2*np+1][0], bf[2*np+1][1], bd);
            }
#pragma unroll
            for (int mt = 0; mt < MT; mt++)
#pragma unroll
                for (int nt = 0; nt < NT; nt++)
                    mma16(acc[mt][nt], af[mt], bf[nt]);
        }
        __syncthreads();          // all warps done reading buf before overwrite
        if (t + 2 < T) { ISSUE_STAGE((t + 2) % 3, t + 2); } else { CP_COMMIT(); }
    }

    // ---- epilogue ----
#pragma unroll
    for (int mt = 0; mt < MT; mt++) {
#pragma unroll
        for (int nt = 0; nt < NT; nt++) {
            const int row = m0 + wm*WTM + mt*16 + qr;
            const int col = n0 + wn*WTN + nt*8 + 2*qc;
            float2 bv = *(const float2*)(bias + col);
            float x0 = acc[mt][nt][0] + bv.x;
            float x1 = acc[mt][nt][1] + bv.y;
            float x2 = acc[mt][nt][2] + bv.x;
            float x3 = acc[mt][nt][3] + bv.y;
            if (MODE == 1 || MODE == 3) {
                const float* sp = (MODE == 1) ? g_s1 : g_s3;
                const float* op = (MODE == 1) ? g_o1 : g_o3;
                const float al  = (MODE == 1) ? g_al[0] : g_al[2];
                float2 sv = *(const float2*)(sp + col);
                float2 ov = *(const float2*)(op + col);
                x0 = fmaf(x0, sv.x, ov.x); x0 = x0>=0.f ? x0 : al*x0;
                x1 = fmaf(x1, sv.y, ov.y); x1 = x1>=0.f ? x1 : al*x1;
                x2 = fmaf(x2, sv.x, ov.x); x2 = x2>=0.f ? x2 : al*x2;
                x3 = fmaf(x3, sv.y, ov.y); x3 = x3>=0.f ? x3 : al*x3;
            }
            if (OUTH) {
                __half* C = (__half*)Cst;
                *(uint32_t*)&C[(size_t)row * N + col]       = f2h(x0, x1);
                *(uint32_t*)&C[(size_t)(row + 8) * N + col] = f2h(x2, x3);
            } else {
                float* C = (float*)Cst;
                *(float2*)&C[(size_t)row * N + col]       = make_float2(x0, x1);
                *(float2*)&C[(size_t)(row + 8) * N + col] = make_float2(x2, x3);
            }
        }
    }
#undef ISSUE_STAGE
}

// ---------------- GRU gate elementwise step (fp16 I/O) ----------------------
// Also applies BN2+PReLU when writing hs (hs only feeds the conv GEMM).
__global__ void gate16_kernel(int l)
{
    int idx = blockIdx.x * blockDim.x + threadIdx.x;   // over BB*HH/8
    int j8 = idx % (HH/8);
    int b  = idx / (HH/8);
    const __half* gp = g_gi16 + (size_t)b * GG + j8*8;
    const __half* hp = g_gh16 + (size_t)b * GG + j8*8;

    uint4 gir = *(const uint4*)(gp);
    uint4 giz = *(const uint4*)(gp + HH);
    uint4 gin = *(const uint4*)(gp + 2*HH);
    uint4 ghr = *(const uint4*)(hp);
    uint4 ghz = *(const uint4*)(hp + HH);
    uint4 ghn = *(const uint4*)(hp + 2*HH);
    uint4 hv  = *(const uint4*)(g_h16 + (size_t)b * HH + j8*8);

    float4 s20 = *(const float4*)(g_s2 + j8*8);
    float4 s21 = *(const float4*)(g_s2 + j8*8 + 4);
    float4 o20 = *(const float4*)(g_o2 + j8*8);
    float4 o21 = *(const float4*)(g_o2 + j8*8 + 4);
    const float aA = g_al[1];

    uint32_t ho[4], yo[4];
    const uint32_t* girp = (const uint32_t*)&gir;
    const uint32_t* gizp = (const uint32_t*)&giz;
    const uint32_t* ginp = (const uint32_t*)&gin;
    const uint32_t* ghrp = (const uint32_t*)&ghr;
    const uint32_t* ghzp = (const uint32_t*)&ghz;
    const uint32_t* ghnp = (const uint32_t*)&ghn;
    const uint32_t* hvp  = (const uint32_t*)&hv;
    const float s2a[8] = {s20.x,s20.y,s20.z,s20.w,s21.x,s21.y,s21.z,s21.w};
    const float o2a[8] = {o20.x,o20.y,o20.z,o20.w,o21.x,o21.y,o21.z,o21.w};

#pragma unroll
    for (int p = 0; p < 4; p++) {
        float2 gr = h2f(girp[p]), gz = h2f(gizp[p]), gn = h2f(ginp[p]);
        float2 hr = h2f(ghrp[p]), hz = h2f(ghzp[p]), hn = h2f(ghnp[p]);
        float2 h0 = h2f(hvp[p]);
        float r0 = sigf(gr.x + hr.x), r1 = sigf(gr.y + hr.y);
        float z0 = sigf(gz.x + hz.x), z1 = sigf(gz.y + hz.y);
        float n0 = tanhf(gn.x + r0*hn.x), n1 = tanhf(gn.y + r1*hn.y);
        float hx = (1.f - z0)*n0 + z0*h0.x;
        float hy = (1.f - z1)*n1 + z1*h0.y;
        ho[p] = f2h(hx, hy);
        float yx = fmaf(hx, s2a[2*p],   o2a[2*p]);   yx = yx>=0.f ? yx : aA*yx;
        float yy = fmaf(hy, s2a[2*p+1], o2a[2*p+1]); yy = yy>=0.f ? yy : aA*yy;
        yo[p] = f2h(yx, yy);
    }
    *(uint4*)(g_h16 + (size_t)b * HH + j8*8) = *(uint4*)ho;
    *(uint4*)(g_hs16 + ((size_t)b * LLN + l) * HH + j8*8) = *(uint4*)yo;
}

// ---------------- launch ----------------------------------------------------
#define SMEM_BN128 (3*(128*40 + 128*40)*2)   // 61440
#define SMEM_BN32  (3*(128*40 + 32*40)*2)    // 38400

extern "C" void kernel_launch(void* const* d_in, const int* in_sizes, int n_in,
                              void* d_out, int out_size)
{
    const float* A     = (const float*)d_in[0];
    const float* W_lin = (const float*)d_in[1];
    const float* b_lin = (const float*)d_in[2];
    const float* g1    = (const float*)d_in[3];
    const float* be1   = (const float*)d_in[4];
    const float* m1    = (const float*)d_in[5];
    const float* v1    = (const float*)d_in[6];
    const float* a1    = (const float*)d_in[7];
    const float* W_ih  = (const float*)d_in[8];
    const float* W_hh  = (const float*)d_in[9];
    const float* b_ih  = (const float*)d_in[10];
    const float* b_hh  = (const float*)d_in[11];
    const float* g2    = (const float*)d_in[12];
    const float* be2   = (const float*)d_in[13];
    const float* m2    = (const float*)d_in[14];
    const float* v2    = (const float*)d_in[15];
    const float* a2    = (const float*)d_in[16];
    const float* Wc    = (const float*)d_in[17];
    const float* bc    = (const float*)d_in[18];
    const float* g3    = (const float*)d_in[19];
    const float* be3   = (const float*)d_in[20];
    const float* m3    = (const float*)d_in[21];
    const float* v3    = (const float*)d_in[22];
    const float* a3    = (const float*)d_in[23];
    const float* W_mu  = (const float*)d_in[24];
    const float* b_mu  = (const float*)d_in[25];
    float* out = (float*)d_out;

    __half *pxh, *px16, *pgi16, *pgh16, *ph16, *phs16, *py216;
    __half *pwlin, *pwih, *pwhh, *pwc, *pwmu;
    cudaGetSymbolAddress((void**)&pxh,   g_xh);
    cudaGetSymbolAddress((void**)&px16,  g_x16);
    cudaGetSymbolAddress((void**)&pgi16, g_gi16);
    cudaGetSymbolAddress((void**)&pgh16, g_gh16);
    cudaGetSymbolAddress((void**)&ph16,  g_h16);
    cudaGetSymbolAddress((void**)&phs16, g_hs16);
    cudaGetSymbolAddress((void**)&py216, g_y216);
    cudaGetSymbolAddress((void**)&pwlin, g_wlin16);
    cudaGetSymbolAddress((void**)&pwih,  g_wih16);
    cudaGetSymbolAddress((void**)&pwhh,  g_whh16);
    cudaGetSymbolAddress((void**)&pwc,   g_wc16);
    cudaGetSymbolAddress((void**)&pwmu,  g_wmu16);

    cudaFuncSetAttribute(hgemm2<128,128,4,2,1,true>,  cudaFuncAttributeMaxDynamicSharedMemorySize, SMEM_BN128);
    cudaFuncSetAttribute(hgemm2<128,128,4,2,0,true>,  cudaFuncAttributeMaxDynamicSharedMemorySize, SMEM_BN128);
    cudaFuncSetAttribute(hgemm2<128,128,4,2,3,true>,  cudaFuncAttributeMaxDynamicSharedMemorySize, SMEM_BN128);
    cudaFuncSetAttribute(hgemm2<128,32,4,2,0,false>,  cudaFuncAttributeMaxDynamicSharedMemorySize, SMEM_BN32);

    prep_kernel<<<1, 256>>>(g1, be1, m1, v1, a1, g2, be2, m2, v2, a2, g3, be3, m3, v3, a3);
    zero_h_kernel<<<(BB*HH/8)/256, 256>>>();

    // fp32 -> fp16 conversions
    cvt_kernel<<<(BB*FF/8 + 255)/256, 256>>>(A,     pxh,   BB*FF/8);
    cvt_kernel<<<(HH*FF/8 + 255)/256, 256>>>(W_lin, pwlin, HH*FF/8);
    cvt_kernel<<<(GG*HH/8 + 255)/256, 256>>>(W_ih,  pwih,  GG*HH/8);
    cvt_kernel<<<(GG*HH/8 + 255)/256, 256>>>(W_hh,  pwhh,  GG*HH/8);
    cvt_kernel<<<(HH*HH/8 + 255)/256, 256>>>(Wc,    pwc,   HH*HH/8);
    cvt_kernel<<<(CC*HH/8 + 255)/256, 256>>>(W_mu,  pwmu,  CC*HH/8);

    // x = PReLU(BN1(A @ W_lin^T + b_lin)) : [8192,256], K=640
    hgemm2<128,128,4,2,1,true><<<dim3(HH/128, BB/128), 256, SMEM_BN128>>>(pxh, pwlin, b_lin, px16, BB, HH, FF);

    // gi = x @ W_ih^T + b_ih : [8192,768], K=256
    hgemm2<128,128,4,2,0,true><<<dim3(GG/128, BB/128), 256, SMEM_BN128>>>(px16, pwih, b_ih, pgi16, BB, GG, HH);

    // GRU recurrence
    for (int l = 0; l < LLN; l++) {
        hgemm2<128,128,4,2,0,true><<<dim3(GG/128, BB/128), 256, SMEM_BN128>>>(ph16, pwhh, b_hh, pgh16, BB, GG, HH);
        gate16_kernel<<<(BB*HH/8)/256, 256>>>(l);
    }

    // y2 = PReLU(BN3(hs_bn2 @ Wc^T + bc)) : [163840,256], K=256  (hs pre-BN2'd)
    hgemm2<128,128,4,2,3,true><<<dim3(HH/128, BLM/128), 256, SMEM_BN128>>>(phs16, pwc, bc, py216, BLM, HH, HH);

    // pred = y2 @ W_mu^T + b_mu : [163840,32] fp32 out
    hgemm2<128,32,4,2,0,false><<<dim3(1, BLM/128), 256, SMEM_BN32>>>(py216, pwmu, b_mu, out, BLM, CC, HH);
}

// round 12
// speedup vs baseline: 1.4828x; 1.4828x over previous
#include <cuda_runtime.h>
#include <cuda_fp16.h>
#include <math.h>
#include <stdint.h>

#define EE 64
#define SSZ 128
#define FF 640
#define HH 256
#define GG 768          // 3*H
#define LLN 20
#define CC 32
#define BB (EE*SSZ)     // 8192
#define BLM (BB*LLN)    // 163840
#define EPSV 1e-5f

// ---------------- scratch (static __device__, no allocation) ----------------
__device__ __half g_xh [BB*FF];     // input converted, 10 MB
__device__ __half g_x16[BB*HH];
__device__ __half g_gi16[BB*GG];
__device__ __half g_gh16[BB*GG];
__device__ __half g_h16[BB*HH];
__device__ __half g_hs16[BLM*HH];   // 80 MB, BN2+PReLU already applied
__device__ __half g_y216[BLM*HH];   // 80 MB
__device__ __half g_wlin16[HH*FF];
__device__ __half g_wih16[GG*HH];
__device__ __half g_whh16[GG*HH];
__device__ __half g_wc16[HH*HH];
__device__ __half g_wmu16[CC*HH];
__device__ float g_s1[HH], g_o1[HH];
__device__ float g_s2[HH], g_o2[HH];
__device__ float g_s3[HH], g_o3[HH];
__device__ float g_al[3];

// ---------------- helpers ----------------------------------------------------
__device__ __forceinline__ uint32_t cvta_s(const void* p) {
    return (uint32_t)__cvta_generic_to_shared(p);
}
__device__ __forceinline__ void mma16(float* c, const uint32_t* a, const uint32_t* b) {
    asm volatile("mma.sync.aligned.m16n8k16.row.col.f32.f16.f16.f32 "
        "{%0,%1,%2,%3},{%4,%5,%6,%7},{%8,%9},{%0,%1,%2,%3};"
        : "+f"(c[0]), "+f"(c[1]), "+f"(c[2]), "+f"(c[3])
        : "r"(a[0]), "r"(a[1]), "r"(a[2]), "r"(a[3]), "r"(b[0]), "r"(b[1]));
}
#define LDSM4(r0,r1,r2,r3,addr) \
    asm volatile("ldmatrix.sync.aligned.m8n8.x4.shared.b16 {%0,%1,%2,%3}, [%4];" \
        : "=r"(r0),"=r"(r1),"=r"(r2),"=r"(r3) : "r"(addr))

__device__ __forceinline__ float sigf(float x) { return 1.f / (1.f + expf(-x)); }
__device__ __forceinline__ float2 h2f(uint32_t u) { return __half22float2(*(__half2*)&u); }
__device__ __forceinline__ uint32_t f2h(float a, float b) {
    __half2 h = __floats2half2_rn(a, b); return *(uint32_t*)&h;
}

// ---------------- prep ------------------------------------------------------
__global__ void prep_kernel(const float* g1,const float* b1,const float* m1,const float* v1,const float* a1,
                            const float* g2,const float* b2,const float* m2,const float* v2,const float* a2,
                            const float* g3,const float* b3,const float* m3,const float* v3,const float* a3)
{
    int i = threadIdx.x;
    float s;
    s = g1[i] / sqrtf(v1[i] + EPSV); g_s1[i] = s; g_o1[i] = b1[i] - m1[i]*s;
    s = g2[i] / sqrtf(v2[i] + EPSV); g_s2[i] = s; g_o2[i] = b2[i] - m2[i]*s;
    s = g3[i] / sqrtf(v3[i] + EPSV); g_s3[i] = s; g_o3[i] = b3[i] - m3[i]*s;
    if (i == 0) { g_al[0] = a1[0]; g_al[1] = a2[0]; g_al[2] = a3[0]; }
}

// convert n8*8 floats -> halfs
__global__ void cvt_kernel(const float* __restrict__ s, __half* __restrict__ d, int n8)
{
    int i = blockIdx.x * blockDim.x + threadIdx.x;
    if (i >= n8) return;
    float4 v0 = *(const float4*)(s + i*8);
    float4 v1 = *(const float4*)(s + i*8 + 4);
    uint4 u = make_uint4(f2h(v0.x,v0.y), f2h(v0.z,v0.w), f2h(v1.x,v1.y), f2h(v1.z,v1.w));
    *(uint4*)(d + i*8) = u;
}

__global__ void zero_h_kernel()
{
    int i = blockIdx.x * blockDim.x + threadIdx.x;   // BB*HH/8
    *(uint4*)(g_h16 + (size_t)i*8) = make_uint4(0,0,0,0);
}

// ---------------- fp16 GEMM, register-prefetch double buffer (R9 pipeline) ---
// C = epi(A @ W^T + bias). A:[M,K], W:[N,K] fp16 row-major. BK=32 halfs,
// pitch 40 halfs (80B, ldmatrix conflict-free). 256 thr = 8 warps WM x WN.
// MODE 0: bias. MODE 1: bias+BN1+PReLU. MODE 3: bias+BN3+PReLU.
// OUTH: fp16 output, else fp32.
template<int BM,int BN,int WM,int WN,int MODE,bool OUTH>
__global__ __launch_bounds__(256, 2) void hgemm3(
    const __half* __restrict__ A, const __half* __restrict__ W,
    const float* __restrict__ bias, void* __restrict__ Cst,
    int M, int N, int K)
{
    constexpr int PIT = 40;
    __shared__ __align__(16) __half Ah[2][BM*PIT];
    __shared__ __align__(16) __half Wh[2][BN*PIT];

    const int tid  = threadIdx.x;
    const int wid  = tid >> 5;
    const int lane = tid & 31;
    const int wm   = wid % WM;
    const int wn   = wid / WM;
    constexpr int WTM = BM / WM;
    constexpr int WTN = BN / WN;
    constexpr int MT  = WTM / 16;
    constexpr int NT  = WTN / 8;            // even
    const int qr = lane >> 2, qc = lane & 3;
    const int l8 = lane & 7;

    const int m0 = blockIdx.y * BM;
    const int n0 = blockIdx.x * BN;

    constexpr int ACH = BM * 4;             // 16B chunks per tile (4 per row)
    constexpr int WCH = BN * 4;
    constexpr int AIT = ACH / 256;          // 2 for BM=128
    constexpr int WIT = (WCH + 255) / 256;

    const int r = tid >> 2, c = tid & 3;    // chunk mapping: row, chunk-col

    float acc[MT][NT][4];
#pragma unroll
    for (int i = 0; i < MT; i++)
#pragma unroll
        for (int j = 0; j < NT; j++)
#pragma unroll
            for (int q = 0; q < 4; q++) acc[i][j][q] = 0.f;

    const int T = K / 32;

    // ---- tile 0 ----
    {
#pragma unroll
        for (int it = 0; it < AIT; it++) {
            int rr = r + it*64;
            uint4 v = *(const uint4*)(A + (size_t)(m0 + rr) * K + c*8);
            *(uint4*)&Ah[0][rr*PIT + c*8] = v;
        }
#pragma unroll
        for (int it = 0; it < WIT; it++) {
            int idx = tid + it*256;
            if ((WCH % 256 == 0) || idx < WCH) {
                int rr = idx >> 2, cc = idx & 3;
                uint4 v = *(const uint4*)(W + (size_t)(n0 + rr) * K + cc*8);
                *(uint4*)&Wh[0][rr*PIT + cc*8] = v;
            }
        }
    }
    __syncthreads();

    int buf = 0;
    for (int t = 0; t < T; t++) {
        // prefetch next tile into registers
        uint4 aP[AIT], wP[WIT];
        if (t + 1 < T) {
#pragma unroll
            for (int it = 0; it < AIT; it++) {
                int rr = r + it*64;
                aP[it] = *(const uint4*)(A + (size_t)(m0 + rr) * K + (t+1)*32 + c*8);
            }
#pragma unroll
            for (int it = 0; it < WIT; it++) {
                int idx = tid + it*256;
                if ((WCH % 256 == 0) || idx < WCH) {
                    int rr = idx >> 2, cc = idx & 3;
                    wP[it] = *(const uint4*)(W + (size_t)(n0 + rr) * K + (t+1)*32 + cc*8);
                }
            }
        }

#pragma unroll
        for (int ks = 0; ks < 2; ks++) {
            uint32_t af[MT][4], bf[NT][2];
#pragma unroll
            for (int mt = 0; mt < MT; mt++) {
                const int m  = wm*WTM + mt*16 + l8 + ((lane >> 3) & 1) * 8;
                const int ck = 2*ks + (lane >> 4);
                uint32_t ad = cvta_s(&Ah[buf][m*PIT + ck*8]);
                LDSM4(af[mt][0], af[mt][1], af[mt][2], af[mt][3], ad);
            }
#pragma unroll
            for (int np = 0; np < NT/2; np++) {
                const int n  = wn*WTN + np*16 + l8 + ((lane >> 4) & 1) * 8;
                const int ck = 2*ks + ((lane >> 3) & 1);
                uint32_t bd = cvta_s(&Wh[buf][n*PIT + ck*8]);
                LDSM4(bf[2*np][0], bf[2*np][1], bf[2*np+1][0], bf[2*np+1][1], bd);
            }
#pragma unroll
            for (int mt = 0; mt < MT; mt++)
#pragma unroll
                for (int nt = 0; nt < NT; nt++)
                    mma16(acc[mt][nt], af[mt], bf[nt]);
        }

        if (t + 1 < T) {
            const int nb = buf ^ 1;
#pragma unroll
            for (int it = 0; it < AIT; it++) {
                int rr = r + it*64;
                *(uint4*)&Ah[nb][rr*PIT + c*8] = aP[it];
            }
#pragma unroll
            for (int it = 0; it < WIT; it++) {
                int idx = tid + it*256;
                if ((WCH % 256 == 0) || idx < WCH) {
                    int rr = idx >> 2, cc = idx & 3;
                    *(uint4*)&Wh[nb][rr*PIT + cc*8] = wP[it];
                }
            }
            __syncthreads();
            buf = nb;
        }
    }

    // ---- epilogue ----
#pragma unroll
    for (int mt = 0; mt < MT; mt++) {
#pragma unroll
        for (int nt = 0; nt < NT; nt++) {
            const int row = m0 + wm*WTM + mt*16 + qr;
            const int col = n0 + wn*WTN + nt*8 + 2*qc;
            float2 bv = *(const float2*)(bias + col);
            float x0 = acc[mt][nt][0] + bv.x;
            float x1 = acc[mt][nt][1] + bv.y;
            float x2 = acc[mt][nt][2] + bv.x;
            float x3 = acc[mt][nt][3] + bv.y;
            if (MODE == 1 || MODE == 3) {
                const float* sp = (MODE == 1) ? g_s1 : g_s3;
                const float* op = (MODE == 1) ? g_o1 : g_o3;
                const float al  = (MODE == 1) ? g_al[0] : g_al[2];
                float2 sv = *(const float2*)(sp + col);
                float2 ov = *(const float2*)(op + col);
                x0 = fmaf(x0, sv.x, ov.x); x0 = x0>=0.f ? x0 : al*x0;
                x1 = fmaf(x1, sv.y, ov.y); x1 = x1>=0.f ? x1 : al*x1;
                x2 = fmaf(x2, sv.x, ov.x); x2 = x2>=0.f ? x2 : al*x2;
                x3 = fmaf(x3, sv.y, ov.y); x3 = x3>=0.f ? x3 : al*x3;
            }
            if (OUTH) {
                __half* C = (__half*)Cst;
                *(uint32_t*)&C[(size_t)row * N + col]       = f2h(x0, x1);
                *(uint32_t*)&C[(size_t)(row + 8) * N + col] = f2h(x2, x3);
            } else {
                float* C = (float*)Cst;
                *(float2*)&C[(size_t)row * N + col]       = make_float2(x0, x1);
                *(float2*)&C[(size_t)(row + 8) * N + col] = make_float2(x2, x3);
            }
        }
    }
}

// ---------------- GRU gate elementwise step (fp16 I/O) ----------------------
// Also applies BN2+PReLU when writing hs (hs only feeds the conv GEMM).
__global__ void gate16_kernel(int l)
{
    int idx = blockIdx.x * blockDim.x + threadIdx.x;   // over BB*HH/8
    int j8 = idx % (HH/8);
    int b  = idx / (HH/8);
    const __half* gp = g_gi16 + (size_t)b * GG + j8*8;
    const __half* hp = g_gh16 + (size_t)b * GG + j8*8;

    uint4 gir = *(const uint4*)(gp);
    uint4 giz = *(const uint4*)(gp + HH);
    uint4 gin = *(const uint4*)(gp + 2*HH);
    uint4 ghr = *(const uint4*)(hp);
    uint4 ghz = *(const uint4*)(hp + HH);
    uint4 ghn = *(const uint4*)(hp + 2*HH);
    uint4 hv  = *(const uint4*)(g_h16 + (size_t)b * HH + j8*8);

    float4 s20 = *(const float4*)(g_s2 + j8*8);
    float4 s21 = *(const float4*)(g_s2 + j8*8 + 4);
    float4 o20 = *(const float4*)(g_o2 + j8*8);
    float4 o21 = *(const float4*)(g_o2 + j8*8 + 4);
    const float aA = g_al[1];

    uint32_t ho[4], yo[4];
    const uint32_t* girp = (const uint32_t*)&gir;
    const uint32_t* gizp = (const uint32_t*)&giz;
    const uint32_t* ginp = (const uint32_t*)&gin;
    const uint32_t* ghrp = (const uint32_t*)&ghr;
    const uint32_t* ghzp = (const uint32_t*)&ghz;
    const uint32_t* ghnp = (const uint32_t*)&ghn;
    const uint32_t* hvp  = (const uint32_t*)&hv;
    const float s2a[8] = {s20.x,s20.y,s20.z,s20.w,s21.x,s21.y,s21.z,s21.w};
    const float o2a[8] = {o20.x,o20.y,o20.z,o20.w,o21.x,o21.y,o21.z,o21.w};

#pragma unroll
    for (int p = 0; p < 4; p++) {
        float2 gr = h2f(girp[p]), gz = h2f(gizp[p]), gn = h2f(ginp[p]);
        float2 hr = h2f(ghrp[p]), hz = h2f(ghzp[p]), hn = h2f(ghnp[p]);
        float2 h0 = h2f(hvp[p]);
        float r0 = sigf(gr.x + hr.x), r1 = sigf(gr.y + hr.y);
        float z0 = sigf(gz.x + hz.x), z1 = sigf(gz.y + hz.y);
        float n0 = tanhf(gn.x + r0*hn.x), n1 = tanhf(gn.y + r1*hn.y);
        float hx = (1.f - z0)*n0 + z0*h0.x;
        float hy = (1.f - z1)*n1 + z1*h0.y;
        ho[p] = f2h(hx, hy);
        float yx = fmaf(hx, s2a[2*p],   o2a[2*p]);   yx = yx>=0.f ? yx : aA*yx;
        float yy = fmaf(hy, s2a[2*p+1], o2a[2*p+1]); yy = yy>=0.f ? yy : aA*yy;
        yo[p] = f2h(yx, yy);
    }
    *(uint4*)(g_h16 + (size_t)b * HH + j8*8) = *(uint4*)ho;
    *(uint4*)(g_hs16 + ((size_t)b * LLN + l) * HH + j8*8) = *(uint4*)yo;
}

// ---------------- launch ----------------------------------------------------
extern "C" void kernel_launch(void* const* d_in, const int* in_sizes, int n_in,
                              void* d_out, int out_size)
{
    const float* A     = (const float*)d_in[0];
    const float* W_lin = (const float*)d_in[1];
    const float* b_lin = (const float*)d_in[2];
    const float* g1    = (const float*)d_in[3];
    const float* be1   = (const float*)d_in[4];
    const float* m1    = (const float*)d_in[5];
    const float* v1    = (const float*)d_in[6];
    const float* a1    = (const float*)d_in[7];
    const float* W_ih  = (const float*)d_in[8];
    const float* W_hh  = (const float*)d_in[9];
    const float* b_ih  = (const float*)d_in[10];
    const float* b_hh  = (const float*)d_in[11];
    const float* g2    = (const float*)d_in[12];
    const float* be2   = (const float*)d_in[13];
    const float* m2    = (const float*)d_in[14];
    const float* v2    = (const float*)d_in[15];
    const float* a2    = (const float*)d_in[16];
    const float* Wc    = (const float*)d_in[17];
    const float* bc    = (const float*)d_in[18];
    const float* g3    = (const float*)d_in[19];
    const float* be3   = (const float*)d_in[20];
    const float* m3    = (const float*)d_in[21];
    const float* v3    = (const float*)d_in[22];
    const float* a3    = (const float*)d_in[23];
    const float* W_mu  = (const float*)d_in[24];
    const float* b_mu  = (const float*)d_in[25];
    float* out = (float*)d_out;

    __half *pxh, *px16, *pgi16, *pgh16, *ph16, *phs16, *py216;
    __half *pwlin, *pwih, *pwhh, *pwc, *pwmu;
    cudaGetSymbolAddress((void**)&pxh,   g_xh);
    cudaGetSymbolAddress((void**)&px16,  g_x16);
    cudaGetSymbolAddress((void**)&pgi16, g_gi16);
    cudaGetSymbolAddress((void**)&pgh16, g_gh16);
    cudaGetSymbolAddress((void**)&ph16,  g_h16);
    cudaGetSymbolAddress((void**)&phs16, g_hs16);
    cudaGetSymbolAddress((void**)&py216, g_y216);
    cudaGetSymbolAddress((void**)&pwlin, g_wlin16);
    cudaGetSymbolAddress((void**)&pwih,  g_wih16);
    cudaGetSymbolAddress((void**)&pwhh,  g_whh16);
    cudaGetSymbolAddress((void**)&pwc,   g_wc16);
    cudaGetSymbolAddress((void**)&pwmu,  g_wmu16);

    prep_kernel<<<1, 256>>>(g1, be1, m1, v1, a1, g2, be2, m2, v2, a2, g3, be3, m3, v3, a3);
    zero_h_kernel<<<(BB*HH/8)/256, 256>>>();

    // fp32 -> fp16 conversions
    cvt_kernel<<<(BB*FF/8 + 255)/256, 256>>>(A,     pxh,   BB*FF/8);
    cvt_kernel<<<(HH*FF/8 + 255)/256, 256>>>(W_lin, pwlin, HH*FF/8);
    cvt_kernel<<<(GG*HH/8 + 255)/256, 256>>>(W_ih,  pwih,  GG*HH/8);
    cvt_kernel<<<(GG*HH/8 + 255)/256, 256>>>(W_hh,  pwhh,  GG*HH/8);
    cvt_kernel<<<(HH*HH/8 + 255)/256, 256>>>(Wc,    pwc,   HH*HH/8);
    cvt_kernel<<<(CC*HH/8 + 255)/256, 256>>>(W_mu,  pwmu,  CC*HH/8);

    // x = PReLU(BN1(A @ W_lin^T + b_lin)) : [8192,256], K=640
    hgemm3<128,128,4,2,1,true><<<dim3(HH/128, BB/128), 256>>>(pxh, pwlin, b_lin, px16, BB, HH, FF);

    // gi = x @ W_ih^T + b_ih : [8192,768], K=256
    hgemm3<128,128,4,2,0,true><<<dim3(GG/128, BB/128), 256>>>(px16, pwih, b_ih, pgi16, BB, GG, HH);

    // GRU recurrence
    for (int l = 0; l < LLN; l++) {
        hgemm3<128,128,4,2,0,true><<<dim3(GG/128, BB/128), 256>>>(ph16, pwhh, b_hh, pgh16, BB, GG, HH);
        gate16_kernel<<<(BB*HH/8)/256, 256>>>(l);
    }

    // y2 = PReLU(BN3(hs_bn2 @ Wc^T + bc)) : [163840,256], K=256  (hs pre-BN2'd)
    hgemm3<128,128,4,2,3,true><<<dim3(HH/128, BLM/128), 256>>>(phs16, pwc, bc, py216, BLM, HH, HH);

    // pred = y2 @ W_mu^T + b_mu : [163840,32] fp32 out
    hgemm3<128,32,4,2,0,false><<<dim3(1, BLM/128), 256>>>(py216, pwmu, b_mu, out, BLM, CC, HH);
}